// round 8
// baseline (speedup 1.0000x reference)
#include <cuda_runtime.h>
#include <cuda_fp16.h>
#include <cstdint>

#define HID       128
#define KTYPES    8
#define CH        768        // edges per block -> grid 417 -> ~2.8 CTA/SM
#define NTHREADS  256
#define GROUP     32         // edges per MMA group
#define MST       136        // smem stride (halves) for M tile  (128 + 8 pad)
#define WST       136        // smem stride (halves) for W tile
#define CST       132        // smem stride (floats) for C tile

// dynamic smem layout (bytes):
//  M_s : 128*MST*2        = 34816
//  W_s : 2 * 32*WST*2     = 17408   (double buffered)
//  C_s : 32*CST*4         = 16896
//  bin : CH * 2           = 1536
//  cnt/off/pos : 3*8*4    = 96
#define SMEM_M_OFF   0
#define SMEM_W_OFF   (128*MST*2)
#define SMEM_C_OFF   (SMEM_W_OFF + 2*GROUP*WST*2)
#define SMEM_BIN_OFF (SMEM_C_OFF + GROUP*CST*4)
#define SMEM_CNT_OFF (SMEM_BIN_OFF + CH*2)
#define SMEM_BYTES   (SMEM_CNT_OFF + 3*8*4)

__device__ __forceinline__ uint32_t smem_u32(const void* p) {
    return (uint32_t)__cvta_generic_to_shared(p);
}

__device__ __forceinline__ uint32_t f2h(float a, float b) {
    half2 h = __floats2half2_rn(a, b);
    return *reinterpret_cast<uint32_t*>(&h);
}

extern "C" __global__ void __launch_bounds__(NTHREADS, 3)
matmsg_kernel(const float* __restrict__ hw,
              const float* __restrict__ ef,
              const float* __restrict__ em,
              float* __restrict__ out, int E)
{
    extern __shared__ char smem[];
    half*     M_s   = (half*)(smem + SMEM_M_OFF);     // [128][MST]
    half*     W_s   = (half*)(smem + SMEM_W_OFF);     // [2][32][WST]
    float*    C_s   = (float*)(smem + SMEM_C_OFF);    // [32][CST]
    uint16_t* bin   = (uint16_t*)(smem + SMEM_BIN_OFF);
    int*      s_cnt = (int*)(smem + SMEM_CNT_OFF);
    int*      s_off = s_cnt + 8;
    int*      s_pos = s_off + 8;

    const int tid  = threadIdx.x;
    const int base = blockIdx.x * CH;
    const int nloc = min(CH, E - base);

    if (tid < 8) s_cnt[tid] = 0;
    __syncthreads();

    // ---- Phase 1: per-edge type (argmax of one-hot) + histogram ----
    int ty[CH / NTHREADS];
#pragma unroll
    for (int i = 0; i < CH / NTHREADS; i++) {
        const int l = tid + i * NTHREADS;
        int t = 0;
        if (l < nloc) {
            const float4* fp = (const float4*)(ef + (size_t)(base + l) * KTYPES);
            float4 f0 = fp[0], f1 = fp[1];
            if (f0.y > 0.5f) t = 1;
            if (f0.z > 0.5f) t = 2;
            if (f0.w > 0.5f) t = 3;
            if (f1.x > 0.5f) t = 4;
            if (f1.y > 0.5f) t = 5;
            if (f1.z > 0.5f) t = 6;
            if (f1.w > 0.5f) t = 7;
            atomicAdd(&s_cnt[t], 1);
        }
        ty[i] = t;
    }
    __syncthreads();

    if (tid == 0) {
        int acc = 0;
#pragma unroll
        for (int k = 0; k < KTYPES; k++) {
            s_off[k] = acc; s_pos[k] = acc; acc += s_cnt[k];
        }
    }
    __syncthreads();

    // ---- Phase 2: scatter local indices into per-type bins ----
#pragma unroll
    for (int i = 0; i < CH / NTHREADS; i++) {
        const int l = tid + i * NTHREADS;
        if (l < nloc) {
            int p = atomicAdd(&s_pos[ty[i]], 1);
            bin[p] = (uint16_t)l;
        }
    }
    __syncthreads();

    const int warp = tid >> 5;
    const int lane = tid & 31;
    const int gr_r = tid >> 3;   // row this thread gathers (0..31)
    const int gr_q = tid & 7;    // 16-float chunk of the row
    const int ep_r = tid >> 3;   // epilogue row (0..31)
    const int ep_j = tid & 7;    // epilogue 16-float chunk

    float4 pf[4];                // register prefetch buffer (row chunk)

    // ---- Phase 3: per-type gather (pipelined) + HMMA ----
    for (int k = 0; k < KTYPES; k++) {
        const int nk  = s_cnt[k];
        if (nk == 0) continue;
        const int off = s_off[k];

        __syncthreads();  // all reads of M_s/W_s/C_s from previous type done

        // stage M_k (128x128 fp32) -> fp16 smem, STS.128 chunks
        {
            const float4* mp = (const float4*)(em + (size_t)k * HID * HID);
#pragma unroll
            for (int i = 0; i < 4; i++) {
                const int pi  = tid + i * NTHREADS;   // 16-half chunk id (0..1023)
                const int row = pi >> 3;
                const int chk = pi & 7;
                const float4* s = mp + row * 32 + chk * 4;
                float4 v0 = s[0], v1 = s[1], v2 = s[2], v3 = s[3];
                uint4 u0, u1;
                u0.x = f2h(v0.x, v0.y); u0.y = f2h(v0.z, v0.w);
                u0.z = f2h(v1.x, v1.y); u0.w = f2h(v1.z, v1.w);
                u1.x = f2h(v2.x, v2.y); u1.y = f2h(v2.z, v2.w);
                u1.z = f2h(v3.x, v3.y); u1.w = f2h(v3.z, v3.w);
                uint4* dst = (uint4*)&M_s[row * MST + chk * 16];
                dst[0] = u0; dst[1] = u1;
            }
        }

        const int ngr = (nk + GROUP - 1) / GROUP;

        // -- pipeline prologue --
        // LDG group 0
        if (gr_r < nk) {
            const int eg = base + bin[off + gr_r];
            const float4* wp = (const float4*)(hw + (size_t)eg * HID) + gr_q * 4;
#pragma unroll
            for (int j = 0; j < 4; j++) pf[j] = wp[j];
        }
        // convert + STS.128 group 0 -> buf 0
        {
            uint4* dst = (uint4*)&W_s[gr_r * WST + gr_q * 16];
            if (gr_r < nk) {
                uint4 u0, u1;
                u0.x = f2h(pf[0].x, pf[0].y); u0.y = f2h(pf[0].z, pf[0].w);
                u0.z = f2h(pf[1].x, pf[1].y); u0.w = f2h(pf[1].z, pf[1].w);
                u1.x = f2h(pf[2].x, pf[2].y); u1.y = f2h(pf[2].z, pf[2].w);
                u1.z = f2h(pf[3].x, pf[3].y); u1.w = f2h(pf[3].z, pf[3].w);
                dst[0] = u0; dst[1] = u1;
            } else {
                const uint4 z = make_uint4(0, 0, 0, 0);
                dst[0] = z; dst[1] = z;
            }
        }
        // LDG group 1
        if (ngr > 1) {
            const int gr = GROUP + gr_r;
            if (gr < nk) {
                const int eg = base + bin[off + gr];
                const float4* wp = (const float4*)(hw + (size_t)eg * HID) + gr_q * 4;
#pragma unroll
                for (int j = 0; j < 4; j++) pf[j] = wp[j];
            }
        }
        __syncthreads();  // M_s + W_s buf0 ready

        // hoist M_k fragments for this warp's 16 hid columns (constant per type)
        uint32_t bfr[8][2][2];
#pragma unroll
        for (int ks = 0; ks < 8; ks++) {
#pragma unroll
            for (int ht = 0; ht < 2; ht++) {
                const int nrow = warp * 16 + ht * 8 + (lane & 7);
                const int kcol = ks * 16 + ((lane >> 3) & 1) * 8;
                uint32_t addr = smem_u32(&M_s[nrow * MST + kcol]);
                asm volatile("ldmatrix.sync.aligned.m8n8.x2.shared.b16 {%0,%1}, [%2];"
                             : "=r"(bfr[ks][ht][0]), "=r"(bfr[ks][ht][1]) : "r"(addr));
            }
        }

        for (int g = 0; g < ngr; g++) {
            const half* Wb = &W_s[(g & 1) * GROUP * WST];

            // ---- MMA on group g ----
            float c[2][2][4];
#pragma unroll
            for (int et = 0; et < 2; et++)
#pragma unroll
                for (int ht = 0; ht < 2; ht++)
#pragma unroll
                    for (int j = 0; j < 4; j++) c[et][ht][j] = 0.f;

#pragma unroll
            for (int ks = 0; ks < 8; ks++) {
#pragma unroll
                for (int et = 0; et < 2; et++) {
                    const int arow = et * 16 + (lane & 15);
                    const int acol = ks * 16 + (lane >> 4) * 8;
                    uint32_t addr = smem_u32(&Wb[arow * WST + acol]);
                    uint32_t a0, a1, a2, a3;
                    asm volatile("ldmatrix.sync.aligned.m8n8.x4.shared.b16 {%0,%1,%2,%3}, [%4];"
                                 : "=r"(a0), "=r"(a1), "=r"(a2), "=r"(a3) : "r"(addr));
#pragma unroll
                    for (int ht = 0; ht < 2; ht++) {
                        asm volatile(
                            "mma.sync.aligned.m16n8k16.row.col.f32.f16.f16.f32 "
                            "{%0,%1,%2,%3}, {%4,%5,%6,%7}, {%8,%9}, {%0,%1,%2,%3};"
                            : "+f"(c[et][ht][0]), "+f"(c[et][ht][1]),
                              "+f"(c[et][ht][2]), "+f"(c[et][ht][3])
                            : "r"(a0), "r"(a1), "r"(a2), "r"(a3),
                              "r"(bfr[ks][ht][0]), "r"(bfr[ks][ht][1]));
                    }
                }
            }

            // ---- epilogue: C fragments -> smem, then coalesced STG ----
#pragma unroll
            for (int et = 0; et < 2; et++) {
#pragma unroll
                for (int ht = 0; ht < 2; ht++) {
#pragma unroll
                    for (int hf = 0; hf < 2; hf++) {
                        const int row = et * 16 + (lane >> 2) + hf * 8;
                        const int col = warp * 16 + ht * 8 + (lane & 3) * 2;
                        *(float2*)&C_s[row * CST + col] =
                            make_float2(c[et][ht][hf * 2], c[et][ht][hf * 2 + 1]);
                    }
                }
            }
            __syncthreads();   // C_s complete; W reads of buf(g) also done

            {
                const int gr = g * GROUP + ep_r;
                if (gr < nk) {
                    const int eg = base + bin[off + gr];
                    float4* op = (float4*)(out + (size_t)eg * HID + ep_j * 16);
                    const float4* cp = (const float4*)&C_s[ep_r * CST + ep_j * 16];
                    op[0] = cp[0]; op[1] = cp[1]; op[2] = cp[2]; op[3] = cp[3];
                }
            }

            // ---- feed pipeline: STS group g+1 (loaded), LDG group g+2 ----
            if (g + 1 < ngr) {
                const int gr1 = (g + 1) * GROUP + gr_r;
                uint4* dst = (uint4*)&W_s[((g + 1) & 1) * GROUP * WST + gr_r * WST + gr_q * 16];
                if (gr1 < nk) {
                    uint4 u0, u1;
                    u0.x = f2h(pf[0].x, pf[0].y); u0.y = f2h(pf[0].z, pf[0].w);
                    u0.z = f2h(pf[1].x, pf[1].y); u0.w = f2h(pf[1].z, pf[1].w);
                    u1.x = f2h(pf[2].x, pf[2].y); u1.y = f2h(pf[2].z, pf[2].w);
                    u1.z = f2h(pf[3].x, pf[3].y); u1.w = f2h(pf[3].z, pf[3].w);
                    dst[0] = u0; dst[1] = u1;
                } else {
                    const uint4 z = make_uint4(0, 0, 0, 0);
                    dst[0] = z; dst[1] = z;
                }
                if (g + 2 < ngr) {
                    const int gr2 = (g + 2) * GROUP + gr_r;
                    if (gr2 < nk) {
                        const int eg = base + bin[off + gr2];
                        const float4* wp = (const float4*)(hw + (size_t)eg * HID) + gr_q * 4;
#pragma unroll
                        for (int j = 0; j < 4; j++) pf[j] = wp[j];
                    }
                }
                __syncthreads();  // STS(g+1) visible; C_s fully read before reuse
            }
        } // groups
    } // k
}

extern "C" void kernel_launch(void* const* d_in, const int* in_sizes, int n_in,
                              void* d_out, int out_size) {
    // inputs (metadata order): h_v (unused), h_w, edge_features, edge_matrices
    const float* hw = (const float*)d_in[1];
    const float* ef = (const float*)d_in[2];
    const float* em = (const float*)d_in[3];
    float* out = (float*)d_out;
    const int E = in_sizes[1] / HID;
    const int grid = (E + CH - 1) / CH;

    cudaFuncSetAttribute(matmsg_kernel,
                         cudaFuncAttributeMaxDynamicSharedMemorySize, SMEM_BYTES);
    matmsg_kernel<<<grid, NTHREADS, SMEM_BYTES>>>(hw, ef, em, out, E);
}

// round 9
// speedup vs baseline: 1.2551x; 1.2551x over previous
#include <cuda_runtime.h>
#include <cuda_fp16.h>
#include <cstdint>

#define HID       128
#define KTYPES    8
#define CH        768        // edges per main-kernel block
#define NTHREADS  256
#define GROUP     32         // edges per MMA group
#define MST       136        // smem stride (halves) for M tile  (128 + 8 pad)
#define WST       136        // smem stride (halves) for W tile
#define EPB       2048       // edges per sort block
#define EMAX      327680
#define NBMAX     ((EMAX + EPB - 1) / EPB)

// dynamic smem (main kernel): M_s 34816 + W_s(2 buf) 17408
#define SMEM_M_OFF   0
#define SMEM_W_OFF   (128*MST*2)
#define SMEM_BYTES   (SMEM_W_OFF + 2*GROUP*WST*2)

// ---- global scratch (static device allocations are allowed) ----
__device__ int g_hist[NBMAX][KTYPES];
__device__ int g_blkoff[NBMAX][KTYPES];
__device__ int g_typeoff[KTYPES + 1];
__device__ int g_sorted[EMAX];

__device__ __forceinline__ uint32_t smem_u32(const void* p) {
    return (uint32_t)__cvta_generic_to_shared(p);
}

__device__ __forceinline__ int decode_type(const float* __restrict__ ef, int e) {
    const float4* fp = (const float4*)(ef + (size_t)e * KTYPES);
    float4 f0 = fp[0], f1 = fp[1];
    int t = 0;
    if (f0.y > 0.5f) t = 1;
    if (f0.z > 0.5f) t = 2;
    if (f0.w > 0.5f) t = 3;
    if (f1.x > 0.5f) t = 4;
    if (f1.y > 0.5f) t = 5;
    if (f1.z > 0.5f) t = 6;
    if (f1.w > 0.5f) t = 7;
    return t;
}

// ---- K1: per-block type histogram ----
extern "C" __global__ void __launch_bounds__(256)
hist_kernel(const float* __restrict__ ef, int E) {
    __shared__ int h[KTYPES];
    const int tid = threadIdx.x;
    if (tid < KTYPES) h[tid] = 0;
    __syncthreads();
    const int base = blockIdx.x * EPB;
    for (int i = tid; i < EPB; i += 256) {
        const int e = base + i;
        if (e < E) atomicAdd(&h[decode_type(ef, e)], 1);
    }
    __syncthreads();
    if (tid < KTYPES) g_hist[blockIdx.x][tid] = h[tid];
}

// ---- K2: prefix sums -> per-block scatter bases + global type offsets ----
extern "C" __global__ void __launch_bounds__(32)
scan_kernel(int NB) {
    __shared__ int tot[KTYPES];
    __shared__ int toff[KTYPES + 1];
    const int k = threadIdx.x;
    if (k < KTYPES) {
        int run = 0;
        for (int b = 0; b < NB; b++) { g_blkoff[b][k] = run; run += g_hist[b][k]; }
        tot[k] = run;
    }
    __syncthreads();
    if (k == 0) {
        int acc = 0;
        for (int i = 0; i < KTYPES; i++) { toff[i] = acc; acc += tot[i]; }
        toff[KTYPES] = acc;
    }
    __syncthreads();
    if (k < KTYPES) {
        const int o = toff[k];
        for (int b = 0; b < NB; b++) g_blkoff[b][k] += o;
    }
    if (k <= KTYPES) g_typeoff[k] = toff[k];
}

// ---- K3: scatter edge ids into type-sorted order ----
extern "C" __global__ void __launch_bounds__(256)
scatter_kernel(const float* __restrict__ ef, int E) {
    __shared__ int cur[KTYPES];
    const int tid = threadIdx.x;
    if (tid < KTYPES) cur[tid] = g_blkoff[blockIdx.x][tid];
    __syncthreads();
    const int base = blockIdx.x * EPB;
    for (int i = tid; i < EPB; i += 256) {
        const int e = base + i;
        if (e < E) {
            const int p = atomicAdd(&cur[decode_type(ef, e)], 1);
            g_sorted[p] = e;
        }
    }
}

__device__ __forceinline__ uint32_t f2h(float a, float b) {
    half2 h = __floats2half2_rn(a, b);
    return *reinterpret_cast<uint32_t*>(&h);
}

// ---- K4: main GEMM over type-sorted spans ----
extern "C" __global__ void __launch_bounds__(NTHREADS, 3)
matmsg_main(const float* __restrict__ hw,
            const float* __restrict__ em,
            float* __restrict__ out, int E)
{
    extern __shared__ char smem[];
    half* M_s = (half*)(smem + SMEM_M_OFF);   // [128][MST]
    half* W_s = (half*)(smem + SMEM_W_OFF);   // [2][32][WST]
    __shared__ int toff[KTYPES + 1];

    const int tid = threadIdx.x;
    if (tid <= KTYPES) toff[tid] = g_typeoff[tid];
    __syncthreads();

    const int base = blockIdx.x * CH;
    const int hiB  = min(base + CH, E);

    const int warp = tid >> 5;
    const int lane = tid & 31;
    const int gr_r = tid >> 3;   // row this thread gathers (0..31)
    const int gr_q = tid & 7;    // 16-float chunk of the row

    float4 pf[4];                // register prefetch buffer

    for (int k = 0; k < KTYPES; k++) {
        const int lo = max(base, toff[k]);
        const int hi = min(hiB, toff[k + 1]);
        if (lo >= hi) continue;
        const int nk = hi - lo;

        __syncthreads();  // previous type's reads of M_s/W_s done

        // stage M_k (128x128 fp32) -> fp16 smem, STS.128 chunks
        {
            const float4* mp = (const float4*)(em + (size_t)k * HID * HID);
#pragma unroll
            for (int i = 0; i < 4; i++) {
                const int pi  = tid + i * NTHREADS;   // 16-half chunk id
                const int row = pi >> 3;
                const int chk = pi & 7;
                const float4* s = mp + row * 32 + chk * 4;
                float4 v0 = s[0], v1 = s[1], v2 = s[2], v3 = s[3];
                uint4 u0, u1;
                u0.x = f2h(v0.x, v0.y); u0.y = f2h(v0.z, v0.w);
                u0.z = f2h(v1.x, v1.y); u0.w = f2h(v1.z, v1.w);
                u1.x = f2h(v2.x, v2.y); u1.y = f2h(v2.z, v2.w);
                u1.z = f2h(v3.x, v3.y); u1.w = f2h(v3.z, v3.w);
                uint4* dst = (uint4*)&M_s[row * MST + chk * 16];
                dst[0] = u0; dst[1] = u1;
            }
        }

        const int ngr = (nk + GROUP - 1) / GROUP;

        // -- pipeline prologue --
        if (gr_r < nk) {
            const int eg = __ldg(&g_sorted[lo + gr_r]);
            const float4* wp = (const float4*)(hw + (size_t)eg * HID) + gr_q * 4;
#pragma unroll
            for (int j = 0; j < 4; j++) pf[j] = wp[j];
        }
        {
            uint4* dst = (uint4*)&W_s[gr_r * WST + gr_q * 16];
            if (gr_r < nk) {
                uint4 u0, u1;
                u0.x = f2h(pf[0].x, pf[0].y); u0.y = f2h(pf[0].z, pf[0].w);
                u0.z = f2h(pf[1].x, pf[1].y); u0.w = f2h(pf[1].z, pf[1].w);
                u1.x = f2h(pf[2].x, pf[2].y); u1.y = f2h(pf[2].z, pf[2].w);
                u1.z = f2h(pf[3].x, pf[3].y); u1.w = f2h(pf[3].z, pf[3].w);
                dst[0] = u0; dst[1] = u1;
            } else {
                const uint4 z = make_uint4(0, 0, 0, 0);
                dst[0] = z; dst[1] = z;
            }
        }
        if (ngr > 1) {
            const int gr = GROUP + gr_r;
            if (gr < nk) {
                const int eg = __ldg(&g_sorted[lo + gr]);
                const float4* wp = (const float4*)(hw + (size_t)eg * HID) + gr_q * 4;
#pragma unroll
                for (int j = 0; j < 4; j++) pf[j] = wp[j];
            }
        }
        __syncthreads();  // M_s + W_s buf0 ready

        // hoist M_k fragments (constant for the whole span)
        uint32_t bfr[8][2][2];
#pragma unroll
        for (int ks = 0; ks < 8; ks++) {
#pragma unroll
            for (int ht = 0; ht < 2; ht++) {
                const int nrow = warp * 16 + ht * 8 + (lane & 7);
                const int kcol = ks * 16 + ((lane >> 3) & 1) * 8;
                uint32_t addr = smem_u32(&M_s[nrow * MST + kcol]);
                asm volatile("ldmatrix.sync.aligned.m8n8.x2.shared.b16 {%0,%1}, [%2];"
                             : "=r"(bfr[ks][ht][0]), "=r"(bfr[ks][ht][1]) : "r"(addr));
            }
        }

        for (int g = 0; g < ngr; g++) {
            const half* Wb = &W_s[(g & 1) * GROUP * WST];

            float c[2][2][4];
#pragma unroll
            for (int et = 0; et < 2; et++)
#pragma unroll
                for (int ht = 0; ht < 2; ht++)
#pragma unroll
                    for (int j = 0; j < 4; j++) c[et][ht][j] = 0.f;

#pragma unroll
            for (int ks = 0; ks < 8; ks++) {
#pragma unroll
                for (int et = 0; et < 2; et++) {
                    const int arow = et * 16 + (lane & 15);
                    const int acol = ks * 16 + (lane >> 4) * 8;
                    uint32_t addr = smem_u32(&Wb[arow * WST + acol]);
                    uint32_t a0, a1, a2, a3;
                    asm volatile("ldmatrix.sync.aligned.m8n8.x4.shared.b16 {%0,%1,%2,%3}, [%4];"
                                 : "=r"(a0), "=r"(a1), "=r"(a2), "=r"(a3) : "r"(addr));
#pragma unroll
                    for (int ht = 0; ht < 2; ht++) {
                        asm volatile(
                            "mma.sync.aligned.m16n8k16.row.col.f32.f16.f16.f32 "
                            "{%0,%1,%2,%3}, {%4,%5,%6,%7}, {%8,%9}, {%0,%1,%2,%3};"
                            : "+f"(c[et][ht][0]), "+f"(c[et][ht][1]),
                              "+f"(c[et][ht][2]), "+f"(c[et][ht][3])
                            : "r"(a0), "r"(a1), "r"(a2), "r"(a3),
                              "r"(bfr[ks][ht][0]), "r"(bfr[ks][ht][1]));
                    }
                }
            }

            // epilogue: scatter to out[edge][h] (fire-and-forget STG)
#pragma unroll
            for (int et = 0; et < 2; et++) {
                const int r0 = et * 16 + (lane >> 2);
#pragma unroll
                for (int hf = 0; hf < 2; hf++) {
                    const int r  = r0 + hf * 8;
                    const int gr = g * GROUP + r;
                    if (gr < nk) {
                        const int eg = __ldg(&g_sorted[lo + gr]);
                        float* orow = out + (size_t)eg * HID + warp * 16 + (lane & 3) * 2;
#pragma unroll
                        for (int ht = 0; ht < 2; ht++) {
                            float2 v = make_float2(c[et][ht][hf * 2], c[et][ht][hf * 2 + 1]);
                            *(float2*)(orow + ht * 8) = v;
                        }
                    }
                }
            }

            // feed pipeline: STS group g+1 (in regs), LDG group g+2
            if (g + 1 < ngr) {
                const int gr1 = (g + 1) * GROUP + gr_r;
                uint4* dst = (uint4*)&W_s[((g + 1) & 1) * GROUP * WST + gr_r * WST + gr_q * 16];
                if (gr1 < nk) {
                    uint4 u0, u1;
                    u0.x = f2h(pf[0].x, pf[0].y); u0.y = f2h(pf[0].z, pf[0].w);
                    u0.z = f2h(pf[1].x, pf[1].y); u0.w = f2h(pf[1].z, pf[1].w);
                    u1.x = f2h(pf[2].x, pf[2].y); u1.y = f2h(pf[2].z, pf[2].w);
                    u1.z = f2h(pf[3].x, pf[3].y); u1.w = f2h(pf[3].z, pf[3].w);
                    dst[0] = u0; dst[1] = u1;
                } else {
                    const uint4 z = make_uint4(0, 0, 0, 0);
                    dst[0] = z; dst[1] = z;
                }
                if (g + 2 < ngr) {
                    const int gr2 = (g + 2) * GROUP + gr_r;
                    if (gr2 < nk) {
                        const int eg = __ldg(&g_sorted[lo + gr2]);
                        const float4* wp = (const float4*)(hw + (size_t)eg * HID) + gr_q * 4;
#pragma unroll
                        for (int j = 0; j < 4; j++) pf[j] = wp[j];
                    }
                }
                __syncthreads();  // STS(g+1) visible; reads of buf(g) done
            }
        } // groups
    } // k
}

extern "C" void kernel_launch(void* const* d_in, const int* in_sizes, int n_in,
                              void* d_out, int out_size) {
    // inputs (metadata order): h_v (unused), h_w, edge_features, edge_matrices
    const float* hw = (const float*)d_in[1];
    const float* ef = (const float*)d_in[2];
    const float* em = (const float*)d_in[3];
    float* out = (float*)d_out;
    const int E = in_sizes[1] / HID;
    const int NB = (E + EPB - 1) / EPB;

    hist_kernel<<<NB, 256>>>(ef, E);
    scan_kernel<<<1, 32>>>(NB);
    scatter_kernel<<<NB, 256>>>(ef, E);

    cudaFuncSetAttribute(matmsg_main,
                         cudaFuncAttributeMaxDynamicSharedMemorySize, SMEM_BYTES);
    matmsg_main<<<(E + CH - 1) / CH, NTHREADS, SMEM_BYTES>>>(hw, em, out, E);
}

// round 10
// speedup vs baseline: 1.4803x; 1.1795x over previous
#include <cuda_runtime.h>
#include <cuda_fp16.h>
#include <cstdint>

#define HID       128
#define KTYPES    8
#define CH        768        // edges per main-kernel block
#define NTHREADS  256
#define GROUP     32         // edges per MMA group
#define MST       136        // smem stride (halves) for M tile  (128 + 8 pad)
#define WST       136        // smem stride (halves) for W tile
#define EPB       4096       // edges per sort block
#define EMAX      327680
#define NBMAX     ((EMAX + EPB - 1) / EPB)

// dynamic smem (main kernel): M_s 34816 + W_s(2 buf) 17408
#define SMEM_M_OFF   0
#define SMEM_W_OFF   (128*MST*2)
#define SMEM_BYTES   (SMEM_W_OFF + 2*GROUP*WST*2)

// ---- global scratch (static device arrays are allowed) ----
__device__ int     g_hist[NBMAX][KTYPES];
__device__ int     g_blkoff[NBMAX][KTYPES];
__device__ int     g_typeoff[KTYPES + 1];
__device__ int     g_sorted[EMAX];
__device__ uint8_t g_type[EMAX];

__device__ __forceinline__ uint32_t smem_u32(const void* p) {
    return (uint32_t)__cvta_generic_to_shared(p);
}

__device__ __forceinline__ int decode_type(const float* __restrict__ ef, int e) {
    const float4* fp = (const float4*)(ef + (size_t)e * KTYPES);
    float4 f0 = fp[0], f1 = fp[1];
    int t = 0;
    if (f0.y > 0.5f) t = 1;
    if (f0.z > 0.5f) t = 2;
    if (f0.w > 0.5f) t = 3;
    if (f1.x > 0.5f) t = 4;
    if (f1.y > 0.5f) t = 5;
    if (f1.z > 0.5f) t = 6;
    if (f1.w > 0.5f) t = 7;
    return t;
}

// ---- K1: decode types (store uint8) + per-block histogram ----
extern "C" __global__ void __launch_bounds__(256)
hist_kernel(const float* __restrict__ ef, int E) {
    __shared__ int h[KTYPES];
    const int tid = threadIdx.x;
    if (tid < KTYPES) h[tid] = 0;
    __syncthreads();
    const int base = blockIdx.x * EPB;
    for (int i = tid; i < EPB; i += 256) {
        const int e = base + i;
        if (e < E) {
            const int t = decode_type(ef, e);
            g_type[e] = (uint8_t)t;
            atomicAdd(&h[t], 1);
        }
    }
    __syncthreads();
    if (tid < KTYPES) g_hist[blockIdx.x][tid] = h[tid];
}

// ---- K2: smem-resident prefix sums (one block, parallel load/store) ----
extern "C" __global__ void __launch_bounds__(256)
scan_kernel(int NB) {
    __shared__ int sh[NBMAX][KTYPES];
    __shared__ int tot[KTYPES];
    __shared__ int toff[KTYPES + 1];
    const int tid = threadIdx.x;
    const int n = NB * KTYPES;
    for (int i = tid; i < n; i += 256)
        sh[i / KTYPES][i % KTYPES] = ((const int*)g_hist)[i];
    __syncthreads();
    if (tid < KTYPES) {
        int run = 0;
        for (int b = 0; b < NB; b++) {
            const int v = sh[b][tid];
            sh[b][tid] = run;
            run += v;
        }
        tot[tid] = run;
    }
    __syncthreads();
    if (tid == 0) {
        int acc = 0;
#pragma unroll
        for (int i = 0; i < KTYPES; i++) { toff[i] = acc; acc += tot[i]; }
        toff[KTYPES] = acc;
    }
    __syncthreads();
    for (int i = tid; i < n; i += 256)
        ((int*)g_blkoff)[i] = sh[i / KTYPES][i % KTYPES] + toff[i % KTYPES];
    if (tid <= KTYPES) g_typeoff[tid] = toff[tid];
}

// ---- K3: scatter edge ids into type-sorted order (reads uint8 types) ----
extern "C" __global__ void __launch_bounds__(256)
scatter_kernel(int E) {
    __shared__ int cur[KTYPES];
    const int tid = threadIdx.x;
    if (tid < KTYPES) cur[tid] = g_blkoff[blockIdx.x][tid];
    __syncthreads();
    const int base = blockIdx.x * EPB;
    for (int i = tid; i < EPB; i += 256) {
        const int e = base + i;
        if (e < E) {
            const int p = atomicAdd(&cur[g_type[e]], 1);
            g_sorted[p] = e;
        }
    }
}

__device__ __forceinline__ uint32_t f2h(float a, float b) {
    half2 h = __floats2half2_rn(a, b);
    return *reinterpret_cast<uint32_t*>(&h);
}

// ---- K4: main GEMM over type-sorted spans ----
extern "C" __global__ void __launch_bounds__(NTHREADS, 3)
matmsg_main(const float* __restrict__ hw,
            const float* __restrict__ em,
            float* __restrict__ out, int E)
{
    extern __shared__ char smem[];
    half* M_s = (half*)(smem + SMEM_M_OFF);   // [128][MST]
    half* W_s = (half*)(smem + SMEM_W_OFF);   // [2][32][WST]
    __shared__ int toff[KTYPES + 1];

    const int tid = threadIdx.x;
    if (tid <= KTYPES) toff[tid] = g_typeoff[tid];
    __syncthreads();

    const int base = blockIdx.x * CH;
    const int hiB  = min(base + CH, E);

    const int warp = tid >> 5;
    const int lane = tid & 31;
    const int gr_r = tid >> 3;   // row this thread gathers (0..31)
    const int gr_q = tid & 7;    // 16-float chunk of the row

    float4 pf[4];                // register prefetch buffer

    for (int k = 0; k < KTYPES; k++) {
        const int lo = max(base, toff[k]);
        const int hi = min(hiB, toff[k + 1]);
        if (lo >= hi) continue;
        const int nk = hi - lo;

        __syncthreads();  // previous type's reads of M_s/W_s done

        // stage M_k (128x128 fp32) -> fp16 smem, STS.128 chunks
        {
            const float4* mp = (const float4*)(em + (size_t)k * HID * HID);
#pragma unroll
            for (int i = 0; i < 4; i++) {
                const int pi  = tid + i * NTHREADS;   // 16-half chunk id
                const int row = pi >> 3;
                const int chk = pi & 7;
                const float4* s = mp + row * 32 + chk * 4;
                float4 v0 = s[0], v1 = s[1], v2 = s[2], v3 = s[3];
                uint4 u0, u1;
                u0.x = f2h(v0.x, v0.y); u0.y = f2h(v0.z, v0.w);
                u0.z = f2h(v1.x, v1.y); u0.w = f2h(v1.z, v1.w);
                u1.x = f2h(v2.x, v2.y); u1.y = f2h(v2.z, v2.w);
                u1.z = f2h(v3.x, v3.y); u1.w = f2h(v3.z, v3.w);
                uint4* dst = (uint4*)&M_s[row * MST + chk * 16];
                dst[0] = u0; dst[1] = u1;
            }
        }

        const int ngr = (nk + GROUP - 1) / GROUP;

        // -- pipeline prologue --
        if (gr_r < nk) {
            const int eg = __ldg(&g_sorted[lo + gr_r]);
            const float4* wp = (const float4*)(hw + (size_t)eg * HID) + gr_q * 4;
#pragma unroll
            for (int j = 0; j < 4; j++) pf[j] = wp[j];
        }
        {
            uint4* dst = (uint4*)&W_s[gr_r * WST + gr_q * 16];
            if (gr_r < nk) {
                uint4 u0, u1;
                u0.x = f2h(pf[0].x, pf[0].y); u0.y = f2h(pf[0].z, pf[0].w);
                u0.z = f2h(pf[1].x, pf[1].y); u0.w = f2h(pf[1].z, pf[1].w);
                u1.x = f2h(pf[2].x, pf[2].y); u1.y = f2h(pf[2].z, pf[2].w);
                u1.z = f2h(pf[3].x, pf[3].y); u1.w = f2h(pf[3].z, pf[3].w);
                dst[0] = u0; dst[1] = u1;
            } else {
                const uint4 z = make_uint4(0, 0, 0, 0);
                dst[0] = z; dst[1] = z;
            }
        }
        if (ngr > 1) {
            const int gr = GROUP + gr_r;
            if (gr < nk) {
                const int eg = __ldg(&g_sorted[lo + gr]);
                const float4* wp = (const float4*)(hw + (size_t)eg * HID) + gr_q * 4;
#pragma unroll
                for (int j = 0; j < 4; j++) pf[j] = wp[j];
            }
        }
        __syncthreads();  // M_s + W_s buf0 ready

        // hoist M_k fragments (constant for the whole span)
        uint32_t bfr[8][2][2];
#pragma unroll
        for (int ks = 0; ks < 8; ks++) {
#pragma unroll
            for (int ht = 0; ht < 2; ht++) {
                const int nrow = warp * 16 + ht * 8 + (lane & 7);
                const int kcol = ks * 16 + ((lane >> 3) & 1) * 8;
                uint32_t addr = smem_u32(&M_s[nrow * MST + kcol]);
                asm volatile("ldmatrix.sync.aligned.m8n8.x2.shared.b16 {%0,%1}, [%2];"
                             : "=r"(bfr[ks][ht][0]), "=r"(bfr[ks][ht][1]) : "r"(addr));
            }
        }

        for (int g = 0; g < ngr; g++) {
            const half* Wb = &W_s[(g & 1) * GROUP * WST];

            float c[2][2][4];
#pragma unroll
            for (int et = 0; et < 2; et++)
#pragma unroll
                for (int ht = 0; ht < 2; ht++)
#pragma unroll
                    for (int j = 0; j < 4; j++) c[et][ht][j] = 0.f;

#pragma unroll
            for (int ks = 0; ks < 8; ks++) {
#pragma unroll
                for (int et = 0; et < 2; et++) {
                    const int arow = et * 16 + (lane & 15);
                    const int acol = ks * 16 + (lane >> 4) * 8;
                    uint32_t addr = smem_u32(&Wb[arow * WST + acol]);
                    uint32_t a0, a1, a2, a3;
                    asm volatile("ldmatrix.sync.aligned.m8n8.x4.shared.b16 {%0,%1,%2,%3}, [%4];"
                                 : "=r"(a0), "=r"(a1), "=r"(a2), "=r"(a3) : "r"(addr));
#pragma unroll
                    for (int ht = 0; ht < 2; ht++) {
                        asm volatile(
                            "mma.sync.aligned.m16n8k16.row.col.f32.f16.f16.f32 "
                            "{%0,%1,%2,%3}, {%4,%5,%6,%7}, {%8,%9}, {%0,%1,%2,%3};"
                            : "+f"(c[et][ht][0]), "+f"(c[et][ht][1]),
                              "+f"(c[et][ht][2]), "+f"(c[et][ht][3])
                            : "r"(a0), "r"(a1), "r"(a2), "r"(a3),
                              "r"(bfr[ks][ht][0]), "r"(bfr[ks][ht][1]));
                    }
                }
            }

            // epilogue: scatter to out[edge][h] (fire-and-forget STG)
#pragma unroll
            for (int et = 0; et < 2; et++) {
                const int r0 = et * 16 + (lane >> 2);
#pragma unroll
                for (int hf = 0; hf < 2; hf++) {
                    const int r  = r0 + hf * 8;
                    const int gr = g * GROUP + r;
                    if (gr < nk) {
                        const int eg = __ldg(&g_sorted[lo + gr]);
                        float* orow = out + (size_t)eg * HID + warp * 16 + (lane & 3) * 2;
#pragma unroll
                        for (int ht = 0; ht < 2; ht++) {
                            float2 v = make_float2(c[et][ht][hf * 2], c[et][ht][hf * 2 + 1]);
                            *(float2*)(orow + ht * 8) = v;
                        }
                    }
                }
            }

            // feed pipeline: STS group g+1 (in regs), LDG group g+2
            if (g + 1 < ngr) {
                const int gr1 = (g + 1) * GROUP + gr_r;
                uint4* dst = (uint4*)&W_s[((g + 1) & 1) * GROUP * WST + gr_r * WST + gr_q * 16];
                if (gr1 < nk) {
                    uint4 u0, u1;
                    u0.x = f2h(pf[0].x, pf[0].y); u0.y = f2h(pf[0].z, pf[0].w);
                    u0.z = f2h(pf[1].x, pf[1].y); u0.w = f2h(pf[1].z, pf[1].w);
                    u1.x = f2h(pf[2].x, pf[2].y); u1.y = f2h(pf[2].z, pf[2].w);
                    u1.z = f2h(pf[3].x, pf[3].y); u1.w = f2h(pf[3].z, pf[3].w);
                    dst[0] = u0; dst[1] = u1;
                } else {
                    const uint4 z = make_uint4(0, 0, 0, 0);
                    dst[0] = z; dst[1] = z;
                }
                if (g + 2 < ngr) {
                    const int gr2 = (g + 2) * GROUP + gr_r;
                    if (gr2 < nk) {
                        const int eg = __ldg(&g_sorted[lo + gr2]);
                        const float4* wp = (const float4*)(hw + (size_t)eg * HID) + gr_q * 4;
#pragma unroll
                        for (int j = 0; j < 4; j++) pf[j] = wp[j];
                    }
                }
                __syncthreads();  // STS(g+1) visible; reads of buf(g) done
            }
        } // groups
    } // k
}

extern "C" void kernel_launch(void* const* d_in, const int* in_sizes, int n_in,
                              void* d_out, int out_size) {
    // inputs (metadata order): h_v (unused), h_w, edge_features, edge_matrices
    const float* hw = (const float*)d_in[1];
    const float* ef = (const float*)d_in[2];
    const float* em = (const float*)d_in[3];
    float* out = (float*)d_out;
    const int E = in_sizes[1] / HID;
    const int NB = (E + EPB - 1) / EPB;

    hist_kernel<<<NB, 256>>>(ef, E);
    scan_kernel<<<1, 256>>>(NB);
    scatter_kernel<<<NB, 256>>>(E);

    cudaFuncSetAttribute(matmsg_main,
                         cudaFuncAttributeMaxDynamicSharedMemorySize, SMEM_BYTES);
    matmsg_main<<<(E + CH - 1) / CH, NTHREADS, SMEM_BYTES>>>(hw, em, out, E);
}

// round 11
// speedup vs baseline: 1.5616x; 1.0549x over previous
#include <cuda_runtime.h>
#include <cuda_fp16.h>
#include <cstdint>

#define HID       128
#define KTYPES    8
#define CH        768        // edges per main-kernel block
#define NTHREADS  256
#define GROUP     32         // edges per MMA group
#define MST       136        // smem stride (halves) for M tile  (128 + 8 pad)
#define WST       136        // smem stride (halves) for W tile
#define EPB       4096       // edges per sort block
#define EMAX      327680

// dynamic smem (main kernel): M_s 34816 + W_s(2 buf) 17408
#define SMEM_M_OFF   0
#define SMEM_W_OFF   (128*MST*2)
#define SMEM_BYTES   (SMEM_W_OFF + 2*GROUP*WST*2)

// ---- global scratch (static device arrays are allowed) ----
__device__ int g_cnt[KTYPES];
__device__ int g_region[KTYPES][EMAX];   // per-type edge-id lists

__device__ __forceinline__ uint32_t smem_u32(const void* p) {
    return (uint32_t)__cvta_generic_to_shared(p);
}

__device__ __forceinline__ int decode_type(const float* __restrict__ ef, int e) {
    const float4* fp = (const float4*)(ef + (size_t)e * KTYPES);
    float4 f0 = fp[0], f1 = fp[1];
    int t = 0;
    if (f0.y > 0.5f) t = 1;
    if (f0.z > 0.5f) t = 2;
    if (f0.w > 0.5f) t = 3;
    if (f1.x > 0.5f) t = 4;
    if (f1.y > 0.5f) t = 5;
    if (f1.z > 0.5f) t = 6;
    if (f1.w > 0.5f) t = 7;
    return t;
}

// ---- K0: reset type counters (graph-replay safe) ----
extern "C" __global__ void zero_kernel() {
    if (threadIdx.x < KTYPES) g_cnt[threadIdx.x] = 0;
}

// ---- K1: fused decode + block-aggregated append into per-type regions ----
extern "C" __global__ void __launch_bounds__(256)
bin_kernel(const float* __restrict__ ef, int E) {
    __shared__ int h[KTYPES];
    __shared__ int cur[KTYPES];
    const int tid  = threadIdx.x;
    const int base = blockIdx.x * EPB;
    if (tid < KTYPES) h[tid] = 0;
    __syncthreads();

    int ty[EPB / 256];
#pragma unroll
    for (int i = 0; i < EPB / 256; i++) {
        const int e = base + tid + i * 256;
        int t = 0;
        if (e < E) {
            t = decode_type(ef, e);
            atomicAdd(&h[t], 1);
        }
        ty[i] = t;
    }
    __syncthreads();
    if (tid < KTYPES) cur[tid] = atomicAdd(&g_cnt[tid], h[tid]);  // reserve slice
    __syncthreads();
#pragma unroll
    for (int i = 0; i < EPB / 256; i++) {
        const int e = base + tid + i * 256;
        if (e < E) {
            const int t = ty[i];
            const int p = atomicAdd(&cur[t], 1);
            g_region[t][p] = e;
        }
    }
}

__device__ __forceinline__ uint32_t f2h(float a, float b) {
    half2 h = __floats2half2_rn(a, b);
    return *reinterpret_cast<uint32_t*>(&h);
}

// ---- K2: main GEMM over virtually-sorted spans ----
extern "C" __global__ void __launch_bounds__(NTHREADS, 3)
matmsg_main(const float* __restrict__ hw,
            const float* __restrict__ em,
            float* __restrict__ out, int E)
{
    extern __shared__ char smem[];
    half* M_s = (half*)(smem + SMEM_M_OFF);   // [128][MST]
    half* W_s = (half*)(smem + SMEM_W_OFF);   // [2][32][WST]
    __shared__ int toff[KTYPES + 1];

    const int tid = threadIdx.x;
    if (tid == 0) {
        int acc = 0;
#pragma unroll
        for (int i = 0; i < KTYPES; i++) { toff[i] = acc; acc += g_cnt[i]; }
        toff[KTYPES] = acc;
    }
    __syncthreads();

    const int base = blockIdx.x * CH;
    const int hiB  = min(base + CH, E);

    const int warp = tid >> 5;
    const int lane = tid & 31;
    const int gr_r = tid >> 3;   // row this thread gathers (0..31)
    const int gr_q = tid & 7;    // 16-float chunk of the row

    float4 pf[4];                // register prefetch buffer

    for (int k = 0; k < KTYPES; k++) {
        const int lo = max(base, toff[k]);
        const int hi = min(hiB, toff[k + 1]);
        if (lo >= hi) continue;
        const int nk = hi - lo;
        const int* __restrict__ ridx = &g_region[k][lo - toff[k]];

        __syncthreads();  // previous type's reads of M_s/W_s done

        // stage M_k (128x128 fp32) -> fp16 smem, STS.128 chunks
        {
            const float4* mp = (const float4*)(em + (size_t)k * HID * HID);
#pragma unroll
            for (int i = 0; i < 4; i++) {
                const int pi  = tid + i * NTHREADS;   // 16-half chunk id
                const int row = pi >> 3;
                const int chk = pi & 7;
                const float4* s = mp + row * 32 + chk * 4;
                float4 v0 = s[0], v1 = s[1], v2 = s[2], v3 = s[3];
                uint4 u0, u1;
                u0.x = f2h(v0.x, v0.y); u0.y = f2h(v0.z, v0.w);
                u0.z = f2h(v1.x, v1.y); u0.w = f2h(v1.z, v1.w);
                u1.x = f2h(v2.x, v2.y); u1.y = f2h(v2.z, v2.w);
                u1.z = f2h(v3.x, v3.y); u1.w = f2h(v3.z, v3.w);
                uint4* dst = (uint4*)&M_s[row * MST + chk * 16];
                dst[0] = u0; dst[1] = u1;
            }
        }

        const int ngr = (nk + GROUP - 1) / GROUP;

        // -- pipeline prologue --
        if (gr_r < nk) {
            const int eg = __ldg(&ridx[gr_r]);
            const float4* wp = (const float4*)(hw + (size_t)eg * HID) + gr_q * 4;
#pragma unroll
            for (int j = 0; j < 4; j++) pf[j] = wp[j];
        }
        {
            uint4* dst = (uint4*)&W_s[gr_r * WST + gr_q * 16];
            if (gr_r < nk) {
                uint4 u0, u1;
                u0.x = f2h(pf[0].x, pf[0].y); u0.y = f2h(pf[0].z, pf[0].w);
                u0.z = f2h(pf[1].x, pf[1].y); u0.w = f2h(pf[1].z, pf[1].w);
                u1.x = f2h(pf[2].x, pf[2].y); u1.y = f2h(pf[2].z, pf[2].w);
                u1.z = f2h(pf[3].x, pf[3].y); u1.w = f2h(pf[3].z, pf[3].w);
                dst[0] = u0; dst[1] = u1;
            } else {
                const uint4 z = make_uint4(0, 0, 0, 0);
                dst[0] = z; dst[1] = z;
            }
        }
        if (ngr > 1) {
            const int gr = GROUP + gr_r;
            if (gr < nk) {
                const int eg = __ldg(&ridx[gr]);
                const float4* wp = (const float4*)(hw + (size_t)eg * HID) + gr_q * 4;
#pragma unroll
                for (int j = 0; j < 4; j++) pf[j] = wp[j];
            }
        }
        __syncthreads();  // M_s + W_s buf0 ready

        // hoist M_k fragments (constant for the whole span)
        uint32_t bfr[8][2][2];
#pragma unroll
        for (int ks = 0; ks < 8; ks++) {
#pragma unroll
            for (int ht = 0; ht < 2; ht++) {
                const int nrow = warp * 16 + ht * 8 + (lane & 7);
                const int kcol = ks * 16 + ((lane >> 3) & 1) * 8;
                uint32_t addr = smem_u32(&M_s[nrow * MST + kcol]);
                asm volatile("ldmatrix.sync.aligned.m8n8.x2.shared.b16 {%0,%1}, [%2];"
                             : "=r"(bfr[ks][ht][0]), "=r"(bfr[ks][ht][1]) : "r"(addr));
            }
        }

        for (int g = 0; g < ngr; g++) {
            const half* Wb = &W_s[(g & 1) * GROUP * WST];

            float c[2][2][4];
#pragma unroll
            for (int et = 0; et < 2; et++)
#pragma unroll
                for (int ht = 0; ht < 2; ht++)
#pragma unroll
                    for (int j = 0; j < 4; j++) c[et][ht][j] = 0.f;

#pragma unroll
            for (int ks = 0; ks < 8; ks++) {
#pragma unroll
                for (int et = 0; et < 2; et++) {
                    const int arow = et * 16 + (lane & 15);
                    const int acol = ks * 16 + (lane >> 4) * 8;
                    uint32_t addr = smem_u32(&Wb[arow * WST + acol]);
                    uint32_t a0, a1, a2, a3;
                    asm volatile("ldmatrix.sync.aligned.m8n8.x4.shared.b16 {%0,%1,%2,%3}, [%4];"
                                 : "=r"(a0), "=r"(a1), "=r"(a2), "=r"(a3) : "r"(addr));
#pragma unroll
                    for (int ht = 0; ht < 2; ht++) {
                        asm volatile(
                            "mma.sync.aligned.m16n8k16.row.col.f32.f16.f16.f32 "
                            "{%0,%1,%2,%3}, {%4,%5,%6,%7}, {%8,%9}, {%0,%1,%2,%3};"
                            : "+f"(c[et][ht][0]), "+f"(c[et][ht][1]),
                              "+f"(c[et][ht][2]), "+f"(c[et][ht][3])
                            : "r"(a0), "r"(a1), "r"(a2), "r"(a3),
                              "r"(bfr[ks][ht][0]), "r"(bfr[ks][ht][1]));
                    }
                }
            }

            // epilogue: scatter to out[edge][h] (fire-and-forget STG)
#pragma unroll
            for (int et = 0; et < 2; et++) {
                const int r0 = et * 16 + (lane >> 2);
#pragma unroll
                for (int hf = 0; hf < 2; hf++) {
                    const int r  = r0 + hf * 8;
                    const int gr = g * GROUP + r;
                    if (gr < nk) {
                        const int eg = __ldg(&ridx[gr]);
                        float* orow = out + (size_t)eg * HID + warp * 16 + (lane & 3) * 2;
#pragma unroll
                        for (int ht = 0; ht < 2; ht++) {
                            float2 v = make_float2(c[et][ht][hf * 2], c[et][ht][hf * 2 + 1]);
                            *(float2*)(orow + ht * 8) = v;
                        }
                    }
                }
            }

            // feed pipeline: STS group g+1 (in regs), LDG group g+2
            if (g + 1 < ngr) {
                const int gr1 = (g + 1) * GROUP + gr_r;
                uint4* dst = (uint4*)&W_s[((g + 1) & 1) * GROUP * WST + gr_r * WST + gr_q * 16];
                if (gr1 < nk) {
                    uint4 u0, u1;
                    u0.x = f2h(pf[0].x, pf[0].y); u0.y = f2h(pf[0].z, pf[0].w);
                    u0.z = f2h(pf[1].x, pf[1].y); u0.w = f2h(pf[1].z, pf[1].w);
                    u1.x = f2h(pf[2].x, pf[2].y); u1.y = f2h(pf[2].z, pf[2].w);
                    u1.z = f2h(pf[3].x, pf[3].y); u1.w = f2h(pf[3].z, pf[3].w);
                    dst[0] = u0; dst[1] = u1;
                } else {
                    const uint4 z = make_uint4(0, 0, 0, 0);
                    dst[0] = z; dst[1] = z;
                }
                if (g + 2 < ngr) {
                    const int gr2 = (g + 2) * GROUP + gr_r;
                    if (gr2 < nk) {
                        const int eg = __ldg(&ridx[gr2]);
                        const float4* wp = (const float4*)(hw + (size_t)eg * HID) + gr_q * 4;
#pragma unroll
                        for (int j = 0; j < 4; j++) pf[j] = wp[j];
                    }
                }
                __syncthreads();  // STS(g+1) visible; reads of buf(g) done
            }
        } // groups
    } // k
}

extern "C" void kernel_launch(void* const* d_in, const int* in_sizes, int n_in,
                              void* d_out, int out_size) {
    // inputs (metadata order): h_v (unused), h_w, edge_features, edge_matrices
    const float* hw = (const float*)d_in[1];
    const float* ef = (const float*)d_in[2];
    const float* em = (const float*)d_in[3];
    float* out = (float*)d_out;
    const int E = in_sizes[1] / HID;
    const int NB = (E + EPB - 1) / EPB;

    zero_kernel<<<1, 32>>>();
    bin_kernel<<<NB, 256>>>(ef, E);

    cudaFuncSetAttribute(matmsg_main,
                         cudaFuncAttributeMaxDynamicSharedMemorySize, SMEM_BYTES);
    matmsg_main<<<(E + CH - 1) / CH, NTHREADS, SMEM_BYTES>>>(hw, em, out, E);
}

// round 12
// speedup vs baseline: 1.6614x; 1.0639x over previous
#include <cuda_runtime.h>
#include <cuda_fp16.h>
#include <cstdint>

#define HID       128
#define KTYPES    8
#define CH        768        // edges per main-kernel block
#define NTHREADS  256
#define GROUP     32         // edges per MMA group
#define MST       136        // smem stride (halves) for M tile  (128 + 8 pad)
#define WST       136        // smem stride (halves) for W tile
#define EPB       1024       // edges per bin block -> 313 blocks (full chip)
#define EMAX      327680

// dynamic smem (main kernel): M_s 34816 + W_s(2 buf) 17408
#define SMEM_M_OFF   0
#define SMEM_W_OFF   (128*MST*2)
#define SMEM_BYTES   (SMEM_W_OFF + 2*GROUP*WST*2)

// ---- global scratch (static device arrays are allowed) ----
__device__ int g_cnt[KTYPES];
__device__ int g_region[KTYPES][EMAX];   // per-type edge-id lists

__device__ __forceinline__ uint32_t smem_u32(const void* p) {
    return (uint32_t)__cvta_generic_to_shared(p);
}

__device__ __forceinline__ int decode_type(const float* __restrict__ ef, int e) {
    const float4* fp = (const float4*)(ef + (size_t)e * KTYPES);
    float4 f0 = fp[0], f1 = fp[1];
    int t = 0;
    if (f0.y > 0.5f) t = 1;
    if (f0.z > 0.5f) t = 2;
    if (f0.w > 0.5f) t = 3;
    if (f1.x > 0.5f) t = 4;
    if (f1.y > 0.5f) t = 5;
    if (f1.z > 0.5f) t = 6;
    if (f1.w > 0.5f) t = 7;
    return t;
}

// ---- K1: fused decode + block-aggregated append into per-type regions ----
extern "C" __global__ void __launch_bounds__(256)
bin_kernel(const float* __restrict__ ef, int E) {
    __shared__ int h[KTYPES];
    __shared__ int cur[KTYPES];
    const int tid  = threadIdx.x;
    const int base = blockIdx.x * EPB;
    if (tid < KTYPES) h[tid] = 0;
    __syncthreads();

    int ty[EPB / 256];
#pragma unroll
    for (int i = 0; i < EPB / 256; i++) {
        const int e = base + tid + i * 256;
        int t = 0;
        if (e < E) {
            t = decode_type(ef, e);
            atomicAdd(&h[t], 1);
        }
        ty[i] = t;
    }
    __syncthreads();
    if (tid < KTYPES) cur[tid] = atomicAdd(&g_cnt[tid], h[tid]);  // reserve slice
    __syncthreads();
#pragma unroll
    for (int i = 0; i < EPB / 256; i++) {
        const int e = base + tid + i * 256;
        if (e < E) {
            const int t = ty[i];
            const int p = atomicAdd(&cur[t], 1);
            g_region[t][p] = e;
        }
    }
}

__device__ __forceinline__ uint32_t f2h(float a, float b) {
    half2 h = __floats2half2_rn(a, b);
    return *reinterpret_cast<uint32_t*>(&h);
}

// ---- K2: main GEMM over virtually-sorted spans ----
extern "C" __global__ void __launch_bounds__(NTHREADS, 3)
matmsg_main(const float* __restrict__ hw,
            const float* __restrict__ em,
            float* __restrict__ out, int E)
{
    extern __shared__ char smem[];
    half* M_s = (half*)(smem + SMEM_M_OFF);   // [128][MST]
    half* W_s = (half*)(smem + SMEM_W_OFF);   // [2][32][WST]
    __shared__ int toff[KTYPES + 1];

    const int tid = threadIdx.x;
    if (tid == 0) {
        int acc = 0;
#pragma unroll
        for (int i = 0; i < KTYPES; i++) { toff[i] = acc; acc += g_cnt[i]; }
        toff[KTYPES] = acc;
    }
    __syncthreads();

    const int base = blockIdx.x * CH;
    const int hiB  = min(base + CH, E);

    const int warp = tid >> 5;
    const int lane = tid & 31;
    const int gr_r = tid >> 3;   // row this thread gathers (0..31)
    const int gr_q = tid & 7;    // 16-float chunk of the row

    float4 pf[4];                // register prefetch buffer

    for (int k = 0; k < KTYPES; k++) {
        const int lo = max(base, toff[k]);
        const int hi = min(hiB, toff[k + 1]);
        if (lo >= hi) continue;
        const int nk = hi - lo;
        const int* __restrict__ ridx = &g_region[k][lo - toff[k]];

        __syncthreads();  // previous type's reads of M_s/W_s done

        // stage M_k (128x128 fp32) -> fp16 smem, STS.128 chunks
        {
            const float4* mp = (const float4*)(em + (size_t)k * HID * HID);
#pragma unroll
            for (int i = 0; i < 4; i++) {
                const int pi  = tid + i * NTHREADS;   // 16-half chunk id
                const int row = pi >> 3;
                const int chk = pi & 7;
                const float4* s = mp + row * 32 + chk * 4;
                float4 v0 = s[0], v1 = s[1], v2 = s[2], v3 = s[3];
                uint4 u0, u1;
                u0.x = f2h(v0.x, v0.y); u0.y = f2h(v0.z, v0.w);
                u0.z = f2h(v1.x, v1.y); u0.w = f2h(v1.z, v1.w);
                u1.x = f2h(v2.x, v2.y); u1.y = f2h(v2.z, v2.w);
                u1.z = f2h(v3.x, v3.y); u1.w = f2h(v3.z, v3.w);
                uint4* dst = (uint4*)&M_s[row * MST + chk * 16];
                dst[0] = u0; dst[1] = u1;
            }
        }

        const int ngr = (nk + GROUP - 1) / GROUP;

        // -- pipeline prologue --
        if (gr_r < nk) {
            const int eg = __ldg(&ridx[gr_r]);
            const float4* wp = (const float4*)(hw + (size_t)eg * HID) + gr_q * 4;
#pragma unroll
            for (int j = 0; j < 4; j++) pf[j] = wp[j];
        }
        {
            uint4* dst = (uint4*)&W_s[gr_r * WST + gr_q * 16];
            if (gr_r < nk) {
                uint4 u0, u1;
                u0.x = f2h(pf[0].x, pf[0].y); u0.y = f2h(pf[0].z, pf[0].w);
                u0.z = f2h(pf[1].x, pf[1].y); u0.w = f2h(pf[1].z, pf[1].w);
                u1.x = f2h(pf[2].x, pf[2].y); u1.y = f2h(pf[2].z, pf[2].w);
                u1.z = f2h(pf[3].x, pf[3].y); u1.w = f2h(pf[3].z, pf[3].w);
                dst[0] = u0; dst[1] = u1;
            } else {
                const uint4 z = make_uint4(0, 0, 0, 0);
                dst[0] = z; dst[1] = z;
            }
        }
        if (ngr > 1) {
            const int gr = GROUP + gr_r;
            if (gr < nk) {
                const int eg = __ldg(&ridx[gr]);
                const float4* wp = (const float4*)(hw + (size_t)eg * HID) + gr_q * 4;
#pragma unroll
                for (int j = 0; j < 4; j++) pf[j] = wp[j];
            }
        }
        __syncthreads();  // M_s + W_s buf0 ready

        // hoist M_k fragments (constant for the whole span)
        uint32_t bfr[8][2][2];
#pragma unroll
        for (int ks = 0; ks < 8; ks++) {
#pragma unroll
            for (int ht = 0; ht < 2; ht++) {
                const int nrow = warp * 16 + ht * 8 + (lane & 7);
                const int kcol = ks * 16 + ((lane >> 3) & 1) * 8;
                uint32_t addr = smem_u32(&M_s[nrow * MST + kcol]);
                asm volatile("ldmatrix.sync.aligned.m8n8.x2.shared.b16 {%0,%1}, [%2];"
                             : "=r"(bfr[ks][ht][0]), "=r"(bfr[ks][ht][1]) : "r"(addr));
            }
        }

        for (int g = 0; g < ngr; g++) {
            const half* Wb = &W_s[(g & 1) * GROUP * WST];

            float c[2][2][4];
#pragma unroll
            for (int et = 0; et < 2; et++)
#pragma unroll
                for (int ht = 0; ht < 2; ht++)
#pragma unroll
                    for (int j = 0; j < 4; j++) c[et][ht][j] = 0.f;

#pragma unroll
            for (int ks = 0; ks < 8; ks++) {
#pragma unroll
                for (int et = 0; et < 2; et++) {
                    const int arow = et * 16 + (lane & 15);
                    const int acol = ks * 16 + (lane >> 4) * 8;
                    uint32_t addr = smem_u32(&Wb[arow * WST + acol]);
                    uint32_t a0, a1, a2, a3;
                    asm volatile("ldmatrix.sync.aligned.m8n8.x4.shared.b16 {%0,%1,%2,%3}, [%4];"
                                 : "=r"(a0), "=r"(a1), "=r"(a2), "=r"(a3) : "r"(addr));
#pragma unroll
                    for (int ht = 0; ht < 2; ht++) {
                        asm volatile(
                            "mma.sync.aligned.m16n8k16.row.col.f32.f16.f16.f32 "
                            "{%0,%1,%2,%3}, {%4,%5,%6,%7}, {%8,%9}, {%0,%1,%2,%3};"
                            : "+f"(c[et][ht][0]), "+f"(c[et][ht][1]),
                              "+f"(c[et][ht][2]), "+f"(c[et][ht][3])
                            : "r"(a0), "r"(a1), "r"(a2), "r"(a3),
                              "r"(bfr[ks][ht][0]), "r"(bfr[ks][ht][1]));
                    }
                }
            }

            // epilogue: scatter to out[edge][h] (fire-and-forget STG)
#pragma unroll
            for (int et = 0; et < 2; et++) {
                const int r0 = et * 16 + (lane >> 2);
#pragma unroll
                for (int hf = 0; hf < 2; hf++) {
                    const int r  = r0 + hf * 8;
                    const int gr = g * GROUP + r;
                    if (gr < nk) {
                        const int eg = __ldg(&ridx[gr]);
                        float* orow = out + (size_t)eg * HID + warp * 16 + (lane & 3) * 2;
#pragma unroll
                        for (int ht = 0; ht < 2; ht++) {
                            float2 v = make_float2(c[et][ht][hf * 2], c[et][ht][hf * 2 + 1]);
                            *(float2*)(orow + ht * 8) = v;
                        }
                    }
                }
            }

            // feed pipeline: STS group g+1 (in regs), LDG group g+2
            if (g + 1 < ngr) {
                const int gr1 = (g + 1) * GROUP + gr_r;
                uint4* dst = (uint4*)&W_s[((g + 1) & 1) * GROUP * WST + gr_r * WST + gr_q * 16];
                if (gr1 < nk) {
                    uint4 u0, u1;
                    u0.x = f2h(pf[0].x, pf[0].y); u0.y = f2h(pf[0].z, pf[0].w);
                    u0.z = f2h(pf[1].x, pf[1].y); u0.w = f2h(pf[1].z, pf[1].w);
                    u1.x = f2h(pf[2].x, pf[2].y); u1.y = f2h(pf[2].z, pf[2].w);
                    u1.z = f2h(pf[3].x, pf[3].y); u1.w = f2h(pf[3].z, pf[3].w);
                    dst[0] = u0; dst[1] = u1;
                } else {
                    const uint4 z = make_uint4(0, 0, 0, 0);
                    dst[0] = z; dst[1] = z;
                }
                if (g + 2 < ngr) {
                    const int gr2 = (g + 2) * GROUP + gr_r;
                    if (gr2 < nk) {
                        const int eg = __ldg(&ridx[gr2]);
                        const float4* wp = (const float4*)(hw + (size_t)eg * HID) + gr_q * 4;
#pragma unroll
                        for (int j = 0; j < 4; j++) pf[j] = wp[j];
                    }
                }
                __syncthreads();  // STS(g+1) visible; reads of buf(g) done
            }
        } // groups
    } // k
}

extern "C" void kernel_launch(void* const* d_in, const int* in_sizes, int n_in,
                              void* d_out, int out_size) {
    // inputs (metadata order): h_v (unused), h_w, edge_features, edge_matrices
    const float* hw = (const float*)d_in[1];
    const float* ef = (const float*)d_in[2];
    const float* em = (const float*)d_in[3];
    float* out = (float*)d_out;
    const int E = in_sizes[1] / HID;
    const int NB = (E + EPB - 1) / EPB;

    // reset type counters: memset node (graph-capturable, cheaper than a kernel)
    void* cnt_addr = nullptr;
    cudaGetSymbolAddress(&cnt_addr, g_cnt);
    cudaMemsetAsync(cnt_addr, 0, KTYPES * sizeof(int));

    bin_kernel<<<NB, 256>>>(ef, E);

    cudaFuncSetAttribute(matmsg_main,
                         cudaFuncAttributeMaxDynamicSharedMemorySize, SMEM_BYTES);
    matmsg_main<<<(E + CH - 1) / CH, NTHREADS, SMEM_BYTES>>>(hw, em, out, E);
}

// round 13
// speedup vs baseline: 1.7374x; 1.0458x over previous
#include <cuda_runtime.h>
#include <cuda_fp16.h>
#include <cstdint>

#define HID       128
#define KTYPES    8
#define CH        768        // edges per main-kernel block
#define NTHREADS  256
#define GROUP     32         // edges per MMA group
#define MST       136        // smem stride (halves) for M tile  (128 + 8 pad)
#define WST       136        // smem stride (halves) for W tile
#define EPB       1024       // edges per bin block -> 313 blocks (full chip)
#define EMAX      327680

// dynamic smem (main kernel): M_s 34816 + W_s(2 buf) 17408
#define SMEM_M_OFF   0
#define SMEM_W_OFF   (128*MST*2)
#define SMEM_BYTES   (SMEM_W_OFF + 2*GROUP*WST*2)

// ---- global scratch (static device arrays are allowed) ----
__device__ int g_cnt[KTYPES];
__device__ int g_region[KTYPES][EMAX];   // per-type edge-id lists

__device__ __forceinline__ uint32_t smem_u32(const void* p) {
    return (uint32_t)__cvta_generic_to_shared(p);
}

__device__ __forceinline__ int decode_type(const float* __restrict__ ef, int e) {
    const float4* fp = (const float4*)(ef + (size_t)e * KTYPES);
    float4 f0 = fp[0], f1 = fp[1];
    int t = 0;
    if (f0.y > 0.5f) t = 1;
    if (f0.z > 0.5f) t = 2;
    if (f0.w > 0.5f) t = 3;
    if (f1.x > 0.5f) t = 4;
    if (f1.y > 0.5f) t = 5;
    if (f1.z > 0.5f) t = 6;
    if (f1.w > 0.5f) t = 7;
    return t;
}

// ---- K1: fused decode + block-aggregated append into per-type regions ----
extern "C" __global__ void __launch_bounds__(256)
bin_kernel(const float* __restrict__ ef, int E) {
    __shared__ int h[KTYPES];
    __shared__ int cur[KTYPES];
    const int tid  = threadIdx.x;
    const int base = blockIdx.x * EPB;
    if (tid < KTYPES) h[tid] = 0;
    __syncthreads();

    int ty[EPB / 256];
#pragma unroll
    for (int i = 0; i < EPB / 256; i++) {
        const int e = base + tid + i * 256;
        int t = 0;
        if (e < E) {
            t = decode_type(ef, e);
            atomicAdd(&h[t], 1);
        }
        ty[i] = t;
    }
    __syncthreads();
    if (tid < KTYPES) cur[tid] = atomicAdd(&g_cnt[tid], h[tid]);  // reserve slice
    __syncthreads();
#pragma unroll
    for (int i = 0; i < EPB / 256; i++) {
        const int e = base + tid + i * 256;
        if (e < E) {
            const int t = ty[i];
            const int p = atomicAdd(&cur[t], 1);
            g_region[t][p] = e;
        }
    }
}

__device__ __forceinline__ uint32_t f2h(float a, float b) {
    half2 h = __floats2half2_rn(a, b);
    return *reinterpret_cast<uint32_t*>(&h);
}

// ---- K2: main GEMM over virtually-sorted spans ----
extern "C" __global__ void __launch_bounds__(NTHREADS, 3)
matmsg_main(const float* __restrict__ hw,
            const float* __restrict__ em,
            float* __restrict__ out, int E)
{
    extern __shared__ char smem[];
    half* M_s = (half*)(smem + SMEM_M_OFF);   // [128][MST]
    half* W_s = (half*)(smem + SMEM_W_OFF);   // [2][32][WST]
    __shared__ int toff[KTYPES + 1];

    const int tid = threadIdx.x;
    if (tid == 0) {
        int acc = 0;
#pragma unroll
        for (int i = 0; i < KTYPES; i++) { toff[i] = acc; acc += g_cnt[i]; }
        toff[KTYPES] = acc;
    }
    __syncthreads();

    const int base = blockIdx.x * CH;
    const int hiB  = min(base + CH, E);

    const int warp = tid >> 5;
    const int lane = tid & 31;
    const int gr_r = tid >> 3;   // row this thread gathers (0..31)
    const int gr_q = tid & 7;    // 16-float chunk of the row
    const int cq    = lane & 3;
    const int chunk = ((cq & 1) << 1) | (cq >> 1);   // lane-quad -> 4-float chunk

    float4 pf[4];                // register prefetch buffer

    for (int k = 0; k < KTYPES; k++) {
        const int lo = max(base, toff[k]);
        const int hi = min(hiB, toff[k + 1]);
        if (lo >= hi) continue;
        const int nk = hi - lo;
        const int* __restrict__ ridx = &g_region[k][lo - toff[k]];

        __syncthreads();  // previous type's reads of M_s/W_s done

        // stage M_k (128x128 fp32) -> fp16 smem, STS.128 chunks
        {
            const float4* mp = (const float4*)(em + (size_t)k * HID * HID);
#pragma unroll
            for (int i = 0; i < 4; i++) {
                const int pi  = tid + i * NTHREADS;   // 16-half chunk id
                const int row = pi >> 3;
                const int chk = pi & 7;
                const float4* s = mp + row * 32 + chk * 4;
                float4 v0 = s[0], v1 = s[1], v2 = s[2], v3 = s[3];
                uint4 u0, u1;
                u0.x = f2h(v0.x, v0.y); u0.y = f2h(v0.z, v0.w);
                u0.z = f2h(v1.x, v1.y); u0.w = f2h(v1.z, v1.w);
                u1.x = f2h(v2.x, v2.y); u1.y = f2h(v2.z, v2.w);
                u1.z = f2h(v3.x, v3.y); u1.w = f2h(v3.z, v3.w);
                uint4* dst = (uint4*)&M_s[row * MST + chk * 16];
                dst[0] = u0; dst[1] = u1;
            }
        }

        const int ngr = (nk + GROUP - 1) / GROUP;

        // -- pipeline prologue --
        if (gr_r < nk) {
            const int eg = __ldg(&ridx[gr_r]);
            const float4* wp = (const float4*)(hw + (size_t)eg * HID) + gr_q * 4;
#pragma unroll
            for (int j = 0; j < 4; j++) pf[j] = wp[j];
        }
        {
            uint4* dst = (uint4*)&W_s[gr_r * WST + gr_q * 16];
            if (gr_r < nk) {
                uint4 u0, u1;
                u0.x = f2h(pf[0].x, pf[0].y); u0.y = f2h(pf[0].z, pf[0].w);
                u0.z = f2h(pf[1].x, pf[1].y); u0.w = f2h(pf[1].z, pf[1].w);
                u1.x = f2h(pf[2].x, pf[2].y); u1.y = f2h(pf[2].z, pf[2].w);
                u1.z = f2h(pf[3].x, pf[3].y); u1.w = f2h(pf[3].z, pf[3].w);
                dst[0] = u0; dst[1] = u1;
            } else {
                const uint4 z = make_uint4(0, 0, 0, 0);
                dst[0] = z; dst[1] = z;
            }
        }
        if (ngr > 1) {
            const int gr = GROUP + gr_r;
            if (gr < nk) {
                const int eg = __ldg(&ridx[gr]);
                const float4* wp = (const float4*)(hw + (size_t)eg * HID) + gr_q * 4;
#pragma unroll
                for (int j = 0; j < 4; j++) pf[j] = wp[j];
            }
        }
        __syncthreads();  // M_s + W_s buf0 ready

        // hoist M_k fragments (constant for the whole span)
        uint32_t bfr[8][2][2];
#pragma unroll
        for (int ks = 0; ks < 8; ks++) {
#pragma unroll
            for (int ht = 0; ht < 2; ht++) {
                const int nrow = warp * 16 + ht * 8 + (lane & 7);
                const int kcol = ks * 16 + ((lane >> 3) & 1) * 8;
                uint32_t addr = smem_u32(&M_s[nrow * MST + kcol]);
                asm volatile("ldmatrix.sync.aligned.m8n8.x2.shared.b16 {%0,%1}, [%2];"
                             : "=r"(bfr[ks][ht][0]), "=r"(bfr[ks][ht][1]) : "r"(addr));
            }
        }

        for (int g = 0; g < ngr; g++) {
            const half* Wb = &W_s[(g & 1) * GROUP * WST];

            // prefetch this group's epilogue edge ids (hidden under MMA)
            int eg_r[2][2];
#pragma unroll
            for (int et = 0; et < 2; et++)
#pragma unroll
                for (int hf = 0; hf < 2; hf++) {
                    const int gr = g * GROUP + et * 16 + hf * 8 + (lane >> 2);
                    eg_r[et][hf] = (gr < nk) ? __ldg(&ridx[gr]) : -1;
                }

            float c[2][2][4];
#pragma unroll
            for (int et = 0; et < 2; et++)
#pragma unroll
                for (int ht = 0; ht < 2; ht++)
#pragma unroll
                    for (int j = 0; j < 4; j++) c[et][ht][j] = 0.f;

#pragma unroll
            for (int ks = 0; ks < 8; ks++) {
#pragma unroll
                for (int et = 0; et < 2; et++) {
                    const int arow = et * 16 + (lane & 15);
                    const int acol = ks * 16 + (lane >> 4) * 8;
                    uint32_t addr = smem_u32(&Wb[arow * WST + acol]);
                    uint32_t a0, a1, a2, a3;
                    asm volatile("ldmatrix.sync.aligned.m8n8.x4.shared.b16 {%0,%1,%2,%3}, [%4];"
                                 : "=r"(a0), "=r"(a1), "=r"(a2), "=r"(a3) : "r"(addr));
#pragma unroll
                    for (int ht = 0; ht < 2; ht++) {
                        asm volatile(
                            "mma.sync.aligned.m16n8k16.row.col.f32.f16.f16.f32 "
                            "{%0,%1,%2,%3}, {%4,%5,%6,%7}, {%8,%9}, {%0,%1,%2,%3};"
                            : "+f"(c[et][ht][0]), "+f"(c[et][ht][1]),
                              "+f"(c[et][ht][2]), "+f"(c[et][ht][3])
                            : "r"(a0), "r"(a1), "r"(a2), "r"(a3),
                              "r"(bfr[ks][ht][0]), "r"(bfr[ks][ht][1]));
                    }
                }
            }

            // ---- epilogue: 1 bfly shuffle -> 16B/lane coalesced STG.128 ----
            // lane quad cq -> chunk {0,2,1,3}; even lanes keep own ht0 pair and
            // receive partner's ht0 pair; odd lanes keep own ht1 pair and
            // receive partner's ht1 pair (partner = lane^1).
#pragma unroll
            for (int et = 0; et < 2; et++) {
#pragma unroll
                for (int hf = 0; hf < 2; hf++) {
                    float2 v0 = make_float2(c[et][0][hf * 2], c[et][0][hf * 2 + 1]);
                    float2 v1 = make_float2(c[et][1][hf * 2], c[et][1][hf * 2 + 1]);
                    float2 s  = (cq & 1) ? v0 : v1;   // what the partner needs
                    float2 r;
                    r.x = __shfl_xor_sync(0xffffffffu, s.x, 1);
                    r.y = __shfl_xor_sync(0xffffffffu, s.y, 1);
                    float4 w;
                    if (cq & 1) { w.x = r.x;  w.y = r.y;  w.z = v1.x; w.w = v1.y; }
                    else        { w.x = v0.x; w.y = v0.y; w.z = r.x;  w.w = r.y;  }
                    const int eg = eg_r[et][hf];
                    if (eg >= 0)
                        *(float4*)(out + (size_t)eg * HID + warp * 16 + chunk * 4) = w;
                }
            }

            // feed pipeline: STS group g+1 (in regs), LDG group g+2
            if (g + 1 < ngr) {
                const int gr1 = (g + 1) * GROUP + gr_r;
                uint4* dst = (uint4*)&W_s[((g + 1) & 1) * GROUP * WST + gr_r * WST + gr_q * 16];
                if (gr1 < nk) {
                    uint4 u0, u1;
                    u0.x = f2h(pf[0].x, pf[0].y); u0.y = f2h(pf[0].z, pf[0].w);
                    u0.z = f2h(pf[1].x, pf[1].y); u0.w = f2h(pf[1].z, pf[1].w);
                    u1.x = f2h(pf[2].x, pf[2].y); u1.y = f2h(pf[2].z, pf[2].w);
                    u1.z = f2h(pf[3].x, pf[3].y); u1.w = f2h(pf[3].z, pf[3].w);
                    dst[0] = u0; dst[1] = u1;
                } else {
                    const uint4 z = make_uint4(0, 0, 0, 0);
                    dst[0] = z; dst[1] = z;
                }
                if (g + 2 < ngr) {
                    const int gr2 = (g + 2) * GROUP + gr_r;
                    if (gr2 < nk) {
                        const int eg = __ldg(&ridx[gr2]);
                        const float4* wp = (const float4*)(hw + (size_t)eg * HID) + gr_q * 4;
#pragma unroll
                        for (int j = 0; j < 4; j++) pf[j] = wp[j];
                    }
                }
                __syncthreads();  // STS(g+1) visible; reads of buf(g) done
            }
        } // groups
    } // k
}

extern "C" void kernel_launch(void* const* d_in, const int* in_sizes, int n_in,
                              void* d_out, int out_size) {
    // inputs (metadata order): h_v (unused), h_w, edge_features, edge_matrices
    const float* hw = (const float*)d_in[1];
    const float* ef = (const float*)d_in[2];
    const float* em = (const float*)d_in[3];
    float* out = (float*)d_out;
    const int E = in_sizes[1] / HID;
    const int NB = (E + EPB - 1) / EPB;

    // reset type counters: memset node (graph-capturable, cheaper than a kernel)
    void* cnt_addr = nullptr;
    cudaGetSymbolAddress(&cnt_addr, g_cnt);
    cudaMemsetAsync(cnt_addr, 0, KTYPES * sizeof(int));

    bin_kernel<<<NB, 256>>>(ef, E);

    cudaFuncSetAttribute(matmsg_main,
                         cudaFuncAttributeMaxDynamicSharedMemorySize, SMEM_BYTES);
    matmsg_main<<<(E + CH - 1) / CH, NTHREADS, SMEM_BYTES>>>(hw, em, out, E);
}